// round 2
// baseline (speedup 1.0000x reference)
#include <cuda_runtime.h>

#define D      512
#define NCOLS  100000
#define BROWS  1000
#define NFILT  50

// Per-row target score, written by prep_kernel, read by rank_gemm_kernel.
__device__ float g_T[BROWS];

// ---------------------------------------------------------------------------
// Kernel 1: per-row target score t[b], plus base value
//   out[b] = 1 - #(unique filtered indices j with s_j >= t)
// Each dot product is a strict sequential fma chain over k (bit-identical to
// the main kernel's per-column accumulation order).
// NOTE: filter_idx / target are int32 (JAX downcasts int64 without x64 mode).
// ---------------------------------------------------------------------------
__global__ void prep_kernel(const float* __restrict__ q,
                            const float* __restrict__ rhs,
                            const int* __restrict__ fidx,
                            const int* __restrict__ tgt,
                            float* __restrict__ out) {
    int b = blockIdx.x;
    __shared__ int   list[NFILT + 1];
    __shared__ float sv[NFILT + 1];
    int t = threadIdx.x;
    if (t < NFILT) {
        int j = fidx[b * NFILT + t];
        list[t] = min(max(j, 0), NCOLS - 1);   // defensive clamp
    }
    if (t == NFILT) {
        int j = tgt[b];
        list[NFILT] = min(max(j, 0), NCOLS - 1);
    }
    __syncthreads();
    if (t <= NFILT) {
        int j = list[t];
        const float* qb = q + (size_t)b * D;
        float acc = 0.0f;
        #pragma unroll 8
        for (int k = 0; k < D; k++) {
            acc = fmaf(__ldg(qb + k), __ldg(rhs + (size_t)k * NCOLS + j), acc);
        }
        sv[t] = acc;
    }
    __syncthreads();
    if (t == 0) {
        float tv = sv[NFILT];
        g_T[b] = tv;
        float corr = 0.0f;
        for (int i = 0; i <= NFILT; i++) {
            bool uniq = true;
            for (int jj = 0; jj < i; jj++) {
                if (list[jj] == list[i]) { uniq = false; break; }
            }
            if (uniq && sv[i] >= tv) corr += 1.0f;
        }
        out[b] = 1.0f - corr;
    }
}

// ---------------------------------------------------------------------------
// Kernel 2: fused GEMM + count.
// 128x128 block tile, 256 threads, 8x8 per-thread tile, K-step 8.
// Accumulators are packed f32x2 pairs driven by fma.rn.f32x2 (2x fp32 rate
// on sm_103a). Per-column accumulation order: k ascending, single fma chain
// per lane -> bit-identical to prep_kernel's dots.
// Epilogue: per-row count of (s >= t) via shared then global atomics.
// ---------------------------------------------------------------------------
__global__ void __launch_bounds__(256, 2)
rank_gemm_kernel(const float* __restrict__ q,
                 const float* __restrict__ rhs,
                 float* __restrict__ out) {
    __shared__ __align__(16) float As[8][128];   // [k][m]
    __shared__ __align__(16) float Bs[8][128];   // [k][n]
    __shared__ float s_cnt[128];

    const int lid = threadIdx.x;
    const int tx  = lid & 15;          // 0..15  (column group)
    const int ty  = lid >> 4;          // 0..15  (row group)
    const int nBase = blockIdx.x * 128;
    const int mBase = blockIdx.y * 128;

    // Global staging indices
    const int qm = lid & 127;          // row within tile for Q load
    const int qk = (lid >> 7) << 2;    // 0 or 4: k offset for Q float4
    const int bk = lid >> 5;           // 0..7: k row for B load
    const int bn = (lid & 31) << 2;    // 0..124: n offset for B float4

    const float* qptr = q + (size_t)(mBase + qm) * D + qk;
    const bool qvalid = (mBase + qm) < BROWS;
    const float* bptr = rhs + (size_t)bk * NCOLS + nBase + bn;
    const bool bvalid = (nBase + bn + 3) < NCOLS;  // full float4 in bounds

    unsigned long long acc[8][4];
    #pragma unroll
    for (int i = 0; i < 8; i++)
        #pragma unroll
        for (int p = 0; p < 4; p++) acc[i][p] = 0ull;

    float4 qreg = qvalid ? *(const float4*)qptr : make_float4(0.f, 0.f, 0.f, 0.f);
    float4 breg = bvalid ? *(const float4*)bptr : make_float4(0.f, 0.f, 0.f, 0.f);

    for (int kt = 0; kt < D / 8; kt++) {
        // Commit staged registers to shared
        As[qk + 0][qm] = qreg.x;
        As[qk + 1][qm] = qreg.y;
        As[qk + 2][qm] = qreg.z;
        As[qk + 3][qm] = qreg.w;
        *(float4*)&Bs[bk][bn] = breg;
        __syncthreads();

        // Prefetch next k-tile to registers (latency hidden behind compute)
        if (kt < D / 8 - 1) {
            const float* qn = qptr + (kt + 1) * 8;
            const float* bb = bptr + (size_t)(kt + 1) * 8 * NCOLS;
            qreg = qvalid ? *(const float4*)qn : make_float4(0.f, 0.f, 0.f, 0.f);
            breg = bvalid ? *(const float4*)bb : make_float4(0.f, 0.f, 0.f, 0.f);
        }

        #pragma unroll
        for (int kk = 0; kk < 8; kk++) {
            float4 a0 = *(const float4*)&As[kk][ty * 4];
            float4 a1 = *(const float4*)&As[kk][64 + ty * 4];
            ulonglong2 b0 = *(const ulonglong2*)&Bs[kk][tx * 4];
            ulonglong2 b1 = *(const ulonglong2*)&Bs[kk][64 + tx * 4];
            unsigned long long bb[4] = { b0.x, b0.y, b1.x, b1.y };
            float av[8] = { a0.x, a0.y, a0.z, a0.w, a1.x, a1.y, a1.z, a1.w };
            #pragma unroll
            for (int i = 0; i < 8; i++) {
                unsigned long long qq;
                asm("mov.b64 %0, {%1, %1};" : "=l"(qq) : "r"(__float_as_uint(av[i])));
                #pragma unroll
                for (int p = 0; p < 4; p++) {
                    asm("fma.rn.f32x2 %0, %1, %2, %0;"
                        : "+l"(acc[i][p]) : "l"(qq), "l"(bb[p]));
                }
            }
        }
        __syncthreads();
    }

    // ---- epilogue: count s >= t per row ----
    if (lid < 128) s_cnt[lid] = 0.0f;
    __syncthreads();

    #pragma unroll
    for (int i = 0; i < 8; i++) {
        int rl  = (i < 4) ? (ty * 4 + i) : (64 + ty * 4 + (i - 4));
        int row = mBase + rl;
        if (row < BROWS) {
            float tv = g_T[row];
            float cnt = 0.0f;
            #pragma unroll
            for (int p = 0; p < 4; p++) {
                int c0 = nBase + ((p < 2) ? (tx * 4 + p * 2)
                                          : (64 + tx * 4 + (p - 2) * 2));
                float slo = __uint_as_float((unsigned int)(acc[i][p] & 0xffffffffull));
                float shi = __uint_as_float((unsigned int)(acc[i][p] >> 32));
                if (c0     < NCOLS && slo >= tv) cnt += 1.0f;
                if (c0 + 1 < NCOLS && shi >= tv) cnt += 1.0f;
            }
            if (cnt != 0.0f) atomicAdd(&s_cnt[rl], cnt);
        }
    }
    __syncthreads();
    if (lid < 128) {
        int row = mBase + lid;
        if (row < BROWS && s_cnt[lid] != 0.0f) atomicAdd(&out[row], s_cnt[lid]);
    }
}

// ---------------------------------------------------------------------------
// Inputs identified by element count (robust to metadata ordering):
//   q f32[512000], rhs f32[51200000], filter_idx i32[50000], target i32[1000].
// Output f32[1000].
// ---------------------------------------------------------------------------
extern "C" void kernel_launch(void* const* d_in, const int* in_sizes, int n_in,
                              void* d_out, int out_size) {
    const float* q    = nullptr;
    const float* rhs  = nullptr;
    const int*   fidx = nullptr;
    const int*   tgt  = nullptr;

    for (int i = 0; i < n_in; i++) {
        switch (in_sizes[i]) {
            case BROWS * D:      q    = (const float*)d_in[i]; break;
            case D * NCOLS:      rhs  = (const float*)d_in[i]; break;
            case BROWS * NFILT:  fidx = (const int*)d_in[i];   break;
            case BROWS:          tgt  = (const int*)d_in[i];   break;
        }
    }
    float* out = (float*)d_out;

    prep_kernel<<<BROWS, 64>>>(q, rhs, fidx, tgt, out);

    dim3 grid((NCOLS + 127) / 128, (BROWS + 127) / 128);
    rank_gemm_kernel<<<grid, 256>>>(q, rhs, out);
}

// round 4
// speedup vs baseline: 1.9096x; 1.9096x over previous
#include <cuda_runtime.h>
#include <cuda_bf16.h>
#include <cstdint>

#define D      512
#define NCOLS  100000
#define BROWS  1000
#define NFILT  50
#define MPAD   1024
#define NTILES 782            /* 782*128 = 100096 */

// ---------------- scratch ----------------
__device__ __align__(16) unsigned short g_qhi[MPAD * D];
__device__ __align__(16) unsigned short g_qlo[MPAD * D];
__device__ float g_T[BROWS];

// ---------------- helpers (sm_80-class PTX only; no arch-suffix features) ----
__device__ __forceinline__ uint32_t smem_u32(const void* p) {
    uint32_t a;
    asm("{ .reg .u64 t; cvta.to.shared.u64 t, %1; cvt.u32.u64 %0, t; }" : "=r"(a) : "l"(p));
    return a;
}
__device__ __forceinline__ void cp16(uint32_t dst, const void* src) {
    asm volatile("cp.async.cg.shared.global [%0], [%1], 16;" :: "r"(dst), "l"(src));
}
__device__ __forceinline__ void cp16z(uint32_t dst, const void* src, int sz) {
    asm volatile("cp.async.cg.shared.global [%0], [%1], 16, %2;" :: "r"(dst), "l"(src), "r"(sz));
}
__device__ __forceinline__ float lds_f32(uint32_t a) {
    float v; asm volatile("ld.shared.f32 %0, [%1];" : "=f"(v) : "r"(a)); return v;
}
__device__ __forceinline__ void ldm4(uint32_t* r, uint32_t a) {
    asm volatile("ldmatrix.sync.aligned.m8n8.x4.shared.b16 {%0,%1,%2,%3}, [%4];"
                 : "=r"(r[0]), "=r"(r[1]), "=r"(r[2]), "=r"(r[3]) : "r"(a));
}
__device__ __forceinline__ void mma4(float* c, const uint32_t* a, uint32_t b0, uint32_t b1) {
    asm volatile("mma.sync.aligned.m16n8k16.row.col.f32.bf16.bf16.f32 "
                 "{%0,%1,%2,%3}, {%4,%5,%6,%7}, {%8,%9}, {%0,%1,%2,%3};"
                 : "+f"(c[0]), "+f"(c[1]), "+f"(c[2]), "+f"(c[3])
                 : "r"(a[0]), "r"(a[1]), "r"(a[2]), "r"(a[3]), "r"(b0), "r"(b1));
}

// ---------------------------------------------------------------------------
// convert q -> hi/lo bf16, padded to 1024 rows (pad rows zero)
// hi = fp32 truncated to top16 (exact bf16), lo = rn_bf16(x - hi)
// ---------------------------------------------------------------------------
__global__ void conv_q_kernel(const float* __restrict__ q) {
    int gid  = blockIdx.x * 256 + threadIdx.x;
    int base = gid * 8;
    if (base >= MPAD * D) return;
    int row = base >> 9;
    float4 f0, f1;
    if (row < BROWS) {
        f0 = *(const float4*)(q + base);
        f1 = *(const float4*)(q + base + 4);
    } else {
        f0 = make_float4(0.f, 0.f, 0.f, 0.f);
        f1 = f0;
    }
    float x[8] = { f0.x, f0.y, f0.z, f0.w, f1.x, f1.y, f1.z, f1.w };
    unsigned int hiw[4], low[4];
    #pragma unroll
    for (int p = 0; p < 4; p++) {
        unsigned int u0 = __float_as_uint(x[2 * p]);
        unsigned int u1 = __float_as_uint(x[2 * p + 1]);
        hiw[p] = __byte_perm(u0, u1, 0x7632);
        float h0 = __uint_as_float(u0 & 0xFFFF0000u);
        float h1 = __uint_as_float(u1 & 0xFFFF0000u);
        __nv_bfloat162 lp = __floats2bfloat162_rn(x[2 * p] - h0, x[2 * p + 1] - h1);
        low[p] = *(unsigned int*)&lp;
    }
    *(uint4*)(g_qhi + base) = make_uint4(hiw[0], hiw[1], hiw[2], hiw[3]);
    *(uint4*)(g_qlo + base) = make_uint4(low[0], low[1], low[2], low[3]);
}

// ---------------------------------------------------------------------------
// prep: exact-fp32 target score t[b] (warp per dot, MLP=16) and
// out[b] = 1 - #(unique filtered j with s_j >= t)
// ---------------------------------------------------------------------------
__global__ void __launch_bounds__(128)
prep_kernel(const float* __restrict__ q, const float* __restrict__ rhs,
            const int* __restrict__ fidx, const int* __restrict__ tgt,
            float* __restrict__ out) {
    int b = blockIdx.x;
    __shared__ int   list[NFILT + 1];
    __shared__ float sv[NFILT + 1];
    __shared__ float qs[D];
    int tid = threadIdx.x, wid = tid >> 5, lane = tid & 31;
    for (int k = tid; k < D; k += 128) qs[k] = q[b * D + k];
    if (tid < NFILT)  list[tid]   = min(max(fidx[b * NFILT + tid], 0), NCOLS - 1);
    if (tid == NFILT) list[NFILT] = min(max(tgt[b], 0), NCOLS - 1);
    __syncthreads();
    for (int d = wid; d <= NFILT; d += 4) {
        int j = list[d];
        float acc = 0.f;
        #pragma unroll
        for (int e = 0; e < 16; e++) {
            int k = e * 32 + lane;
            acc = fmaf(qs[k], __ldg(rhs + (size_t)k * NCOLS + j), acc);
        }
        #pragma unroll
        for (int o = 16; o; o >>= 1) acc += __shfl_xor_sync(0xFFFFFFFFu, acc, o);
        if (lane == 0) sv[d] = acc;
    }
    __syncthreads();
    if (tid == 0) {
        float tv = sv[NFILT];
        g_T[b] = tv;
        float corr = 0.f;
        for (int i = 0; i <= NFILT; i++) {
            bool uniq = true;
            for (int jj = 0; jj < i; jj++)
                if (list[jj] == list[i]) { uniq = false; break; }
            if (uniq && sv[i] >= tv) corr += 1.f;
        }
        out[b] = 1.f - corr;
    }
}

// ---------------------------------------------------------------------------
// main GEMM (mma.sync bf16 split) + fused rank count
// CTA 256m x 128n, 8 warps (4m x 2n), warp tile 64x64, K-chunk 32, 2 buffers.
// A smem: bf16, rows padded to 40 elems (80B)  -> conflict-free ldmatrix
// B smem: fp32, rows padded to 132 elems (528B)-> conflict-free frag loads
// ---------------------------------------------------------------------------
#define A_BYTES   20480                    /* 256*80 per hi/lo tile */
#define B_OFF     (2 * A_BYTES)            /* 40960 */
#define BUF_BYTES (B_OFF + 32 * 528)       /* 57856 */
#define SMEM_TOT  (2 * BUF_BYTES)          /* 115712 */

__global__ void __launch_bounds__(256, 1)
gemm_mma_kernel(const float* __restrict__ rhs, float* __restrict__ out) {
    extern __shared__ char smem[];
    uint32_t sb = smem_u32(smem);
    const int tid = threadIdx.x, lane = tid & 31, wid = tid >> 5;
    const int warpM = wid & 3, warpN = wid >> 2;
    const int mRow0 = blockIdx.x * 256;
    const int nBase = blockIdx.y * 128;

    float c[4][8][4];
    #pragma unroll
    for (int a = 0; a < 4; a++)
        #pragma unroll
        for (int b = 0; b < 8; b++)
            #pragma unroll
            for (int e = 0; e < 4; e++) c[a][b][e] = 0.f;

    auto load_chunk = [&](int ch, int buf) {
        uint32_t base = sb + buf * BUF_BYTES;
        int k0 = ch * 32;
        #pragma unroll
        for (int i = 0; i < 4; i++) {                 // A hi+lo: 4 cp16 each/thread
            int idx = tid + i * 256;
            int r = idx >> 2, seg = idx & 3;
            uint32_t dst = base + r * 80 + seg * 16;
            size_t go = (size_t)(mRow0 + r) * D + k0 + seg * 8;
            cp16(dst,            g_qhi + go);
            cp16(dst + A_BYTES,  g_qlo + go);
        }
        #pragma unroll
        for (int i = 0; i < 4; i++) {                 // B fp32: 4 cp16/thread
            int idx = tid + i * 256;
            int kr = idx >> 5, seg = idx & 31;
            uint32_t dst = base + B_OFF + kr * 528 + seg * 16;
            int n0 = nBase + seg * 4;
            const float* src = rhs + (size_t)(k0 + kr) * NCOLS + n0;
            cp16z(dst, src, n0 < NCOLS ? 16 : 0);     // zero-fill OOB n (NCOLS%4==0)
        }
        asm volatile("cp.async.commit_group;" ::: "memory");
    };

    load_chunk(0, 0);

    for (int ch = 0; ch < 16; ch++) {
        int buf = ch & 1;
        if (ch < 15) {
            load_chunk(ch + 1, 1 - buf);
            asm volatile("cp.async.wait_group 1;" ::: "memory");
        } else {
            asm volatile("cp.async.wait_group 0;" ::: "memory");
        }
        __syncthreads();

        uint32_t Ab = sb + buf * BUF_BYTES;
        uint32_t Bb = Ab + B_OFF;
        #pragma unroll
        for (int k16 = 0; k16 < 2; k16++) {
            uint32_t AH[4][4], AL[4][4];
            #pragma unroll
            for (int mt = 0; mt < 4; mt++) {
                int r  = warpM * 64 + mt * 16 + ((lane >> 3) & 1) * 8 + (lane & 7);
                int ks = k16 * 2 + (lane >> 4);
                uint32_t addr = Ab + r * 80 + ks * 16;
                ldm4(AH[mt], addr);
                ldm4(AL[mt], addr + A_BYTES);
            }
            int krow = k16 * 16 + (lane & 3) * 2;
            int ncol = warpN * 64 + (lane >> 2);
            uint32_t brow = Bb + krow * 528 + ncol * 4;
            #pragma unroll
            for (int nt = 0; nt < 8; nt++) {
                uint32_t ba = brow + nt * 32;
                float f0 = lds_f32(ba);
                float f1 = lds_f32(ba + 528);
                float f2 = lds_f32(ba + 8 * 528);
                float f3 = lds_f32(ba + 9 * 528);
                unsigned int u0 = __float_as_uint(f0), u1 = __float_as_uint(f1);
                unsigned int u2 = __float_as_uint(f2), u3 = __float_as_uint(f3);
                uint32_t bh0 = __byte_perm(u0, u1, 0x7632);
                uint32_t bh1 = __byte_perm(u2, u3, 0x7632);
                float h0 = __uint_as_float(u0 & 0xFFFF0000u);
                float h1 = __uint_as_float(u1 & 0xFFFF0000u);
                float h2 = __uint_as_float(u2 & 0xFFFF0000u);
                float h3 = __uint_as_float(u3 & 0xFFFF0000u);
                __nv_bfloat162 p0 = __floats2bfloat162_rn(f0 - h0, f1 - h1);
                __nv_bfloat162 p1 = __floats2bfloat162_rn(f2 - h2, f3 - h3);
                uint32_t bl0 = *(uint32_t*)&p0;
                uint32_t bl1 = *(uint32_t*)&p1;
                #pragma unroll
                for (int mt = 0; mt < 4; mt++) {
                    mma4(c[mt][nt], AH[mt], bh0, bh1);   // hi*hi
                    mma4(c[mt][nt], AH[mt], bl0, bl1);   // hi*lo
                    mma4(c[mt][nt], AL[mt], bh0, bh1);   // lo*hi
                }
            }
        }
        __syncthreads();
    }

    // ---- epilogue: count s >= t per row ----
    #pragma unroll
    for (int mt = 0; mt < 4; mt++) {
        #pragma unroll
        for (int h = 0; h < 2; h++) {
            int row = mRow0 + warpM * 64 + mt * 16 + h * 8 + (lane >> 2);
            float tv = (row < BROWS) ? g_T[row] : 0.f;
            float cnt = 0.f;
            #pragma unroll
            for (int nt = 0; nt < 8; nt++) {
                int col = nBase + warpN * 64 + nt * 8 + (lane & 3) * 2;
                if (col < NCOLS) {                     // NCOLS even -> col+1 ok too
                    if (c[mt][nt][h * 2 + 0] >= tv) cnt += 1.f;
                    if (c[mt][nt][h * 2 + 1] >= tv) cnt += 1.f;
                }
            }
            cnt += __shfl_xor_sync(0xFFFFFFFFu, cnt, 1);
            cnt += __shfl_xor_sync(0xFFFFFFFFu, cnt, 2);
            if ((lane & 3) == 0 && row < BROWS && cnt != 0.f)
                atomicAdd(out + row, cnt);
        }
    }
}

// ---------------------------------------------------------------------------
extern "C" void kernel_launch(void* const* d_in, const int* in_sizes, int n_in,
                              void* d_out, int out_size) {
    const float* q    = nullptr;
    const float* rhs  = nullptr;
    const int*   fidx = nullptr;
    const int*   tgt  = nullptr;
    for (int i = 0; i < n_in; i++) {
        switch (in_sizes[i]) {
            case BROWS * D:     q    = (const float*)d_in[i]; break;
            case D * NCOLS:     rhs  = (const float*)d_in[i]; break;
            case BROWS * NFILT: fidx = (const int*)d_in[i];   break;
            case BROWS:         tgt  = (const int*)d_in[i];   break;
        }
    }
    float* out = (float*)d_out;

    cudaFuncSetAttribute(gemm_mma_kernel,
                         cudaFuncAttributeMaxDynamicSharedMemorySize, SMEM_TOT);

    conv_q_kernel<<<256, 256>>>(q);
    prep_kernel<<<BROWS, 128>>>(q, rhs, fidx, tgt, out);
    gemm_mma_kernel<<<dim3(4, NTILES), 256, SMEM_TOT>>>(rhs, out);
}